// round 8
// baseline (speedup 1.0000x reference)
#include <cuda_runtime.h>
#include <cuda_bf16.h>

typedef unsigned long long ULL;

#define NB 32        // batch
#define NS 256       // seq len
#define NE 256       // emb
#define NH 512       // hidden
#define NT 45        // tags
#define NG 2048      // 4*NH

// ---------------- scratch (static device globals: allowed) ----------------
__device__ float g_embeds[NS * NB * NE];           // [s][b][e]     8 MB
__device__ float g_xp[2 * NS * NG * NB];           // [dir][s][j][b] 128 MB
__device__ float g_h[2 * 2 * NB * NH];             // [dir][parity][b][k]
__device__ float g_hs[2 * NS * NB * NH];           // [dir][s][b][k] 32 MB
__device__ float g_em[NB * NS * NT];               // [b][s][t]
__device__ float g_loss[NB];
__device__ unsigned g_bar_cnt[2];
__device__ unsigned g_bar_gen[2];

// ---------------- f32x2 packed FMA ----------------
__device__ __forceinline__ void fma2(ULL &d, ULL a, ULL b) {
    asm("fma.rn.f32x2 %0, %1, %2, %0;" : "+l"(d) : "l"(a), "l"(b));
}
union F4U { float4 f; ULL u[2]; };
union F2U { ULL u; float2 f; };

// ============================================================
// Kernel 1: embedding gather.  grid 8192, block 64
// ============================================================
__global__ void k_gather(const int* __restrict__ x, const float* __restrict__ emb) {
    int row = blockIdx.x;                 // row = s*32 + b
    int s = row >> 5, b = row & 31;
    int tok = x[b * NS + s];
    const float4* src = reinterpret_cast<const float4*>(emb) + tok * (NE / 4);
    float4* dst = reinterpret_cast<float4*>(g_embeds) + row * (NE / 4);
    dst[threadIdx.x] = src[threadIdx.x];
}

// ============================================================
// Kernel 2: input projection GEMM (+bias).
// xp[dir][s][j][b] = sum_e w_ih[dir][j][e]*embeds[s][b][e] + bias[j]
// grid (32, 256, 2), block 256. Tile 64j x 32b, K-tiles of 64.
// ============================================================
__global__ __launch_bounds__(256) void k_inproj(
    const float* __restrict__ w_f, const float* __restrict__ bias_f,
    const float* __restrict__ w_b, const float* __restrict__ bias_b)
{
    __shared__ float sW[64 * 66];
    __shared__ float sX[32 * 66];
    const int jb  = blockIdx.x * 64;
    const int s   = blockIdx.y;
    const int dir = blockIdx.z;
    const float* W    = dir ? w_b : w_f;
    const float* bias = dir ? bias_b : bias_f;
    const int tid = threadIdx.x;
    const int tx = tid & 15, ty = tid >> 4;

    ULL acc[4][2] = {};
    for (int kt = 0; kt < 4; ++kt) {
        const float2* Wg = reinterpret_cast<const float2*>(W);
        float2* sW2 = reinterpret_cast<float2*>(sW);
        #pragma unroll
        for (int i = 0; i < 8; ++i) {
            int idx = tid + 256 * i;
            int r = idx >> 5, c = idx & 31;
            sW2[r * 33 + c] = Wg[(jb + r) * 128 + kt * 32 + c];
        }
        const float2* Xg = reinterpret_cast<const float2*>(g_embeds);
        float2* sX2 = reinterpret_cast<float2*>(sX);
        #pragma unroll
        for (int i = 0; i < 4; ++i) {
            int idx = tid + 256 * i;
            int r = idx >> 5, c = idx & 31;
            sX2[r * 33 + c] = Xg[(s * 32 + r) * 128 + kt * 32 + c];
        }
        __syncthreads();
        const ULL* Wu = reinterpret_cast<const ULL*>(sW);
        const ULL* Xu = reinterpret_cast<const ULL*>(sX);
        #pragma unroll 8
        for (int kp = 0; kp < 32; ++kp) {
            ULL x0 = Xu[tx * 33 + kp];
            ULL x1 = Xu[(tx + 16) * 33 + kp];
            #pragma unroll
            for (int i = 0; i < 4; ++i) {
                ULL w2 = Wu[(ty * 4 + i) * 33 + kp];
                fma2(acc[i][0], w2, x0);
                fma2(acc[i][1], w2, x1);
            }
        }
        __syncthreads();
    }
    #pragma unroll
    for (int i = 0; i < 4; ++i) {
        int j = jb + ty * 4 + i;
        float bv = bias[j];
        F2U a0; a0.u = acc[i][0];
        F2U a1; a1.u = acc[i][1];
        float* outp = g_xp + ((dir * NS + s) * NG + j) * NB;
        outp[tx]      = a0.f.x + a0.f.y + bv;
        outp[tx + 16] = a1.f.x + a1.f.y + bv;
    }
}

// ============================================================
// Kernel 3: persistent bidirectional LSTM recurrence.
// grid 128 (64 CTAs/dir, each owns 8 hidden units = 32 gate rows),
// block 256, dynamic smem 137344 B  -> 1 CTA/SM, all co-resident.
// One 64-CTA barrier per step; h double-buffered in global.
// ============================================================
__global__ __launch_bounds__(256, 1) void k_lstm(
    const float* __restrict__ whh_f, const float* __restrict__ whh_b)
{
    extern __shared__ float sm[];
    float* sW = sm;               // 32 x 516 floats
    float* sH = sm + 16512;       // 32 x 516
    float* sG = sm + 33024;       // 32 x 33
    float* sC = sm + 34080;       // 8 x 32
    const int tid = threadIdx.x;
    const int dir = blockIdx.x >> 6;
    const int d   = blockIdx.x & 63;
    const int u0  = d * 8;
    const float* W = dir ? whh_b : whh_f;

    // load this CTA's 32 gate rows of w_hh into smem (resident all 256 steps)
    {
        const float4* Wg = reinterpret_cast<const float4*>(W);
        float4* sW4 = reinterpret_cast<float4*>(sW);
        for (int idx = tid; idx < 32 * 128; idx += 256) {
            int r = idx >> 7, k4 = idx & 127;
            int grow = ((r >> 3) << 9) + u0 + (r & 7);
            sW4[r * 129 + k4] = Wg[grow * 128 + k4];
        }
    }
    for (int idx = tid; idx < 32 * 516; idx += 256) sH[idx] = 0.f;
    sC[tid] = 0.f;                       // 8*32 = 256 == blockDim
    __shared__ unsigned s_base;
    if (tid == 0) s_base = *(volatile unsigned*)&g_bar_gen[dir];
    __syncthreads();
    const unsigned base_gen = s_base;

    const int r  = tid >> 3;             // dot phase: gate row 0..31
    const int bg = tid & 7;              //            batch group
    const int grow = ((r >> 3) << 9) + u0 + (r & 7);
    const int cb = tid >> 3;             // combine phase: batch 0..31
    const int ui = tid & 7;              //                unit 0..7

    for (int step = 0; step < NS; ++step) {
        const int ts = dir ? (NS - 1 - step) : step;
        if (step > 0) {
            const int p = (step - 1) & 1;
            const float4* Hg = reinterpret_cast<const float4*>(g_h) + (dir * 2 + p) * 32 * 128;
            float4* sH4 = reinterpret_cast<float4*>(sH);
            for (int idx = tid; idx < 32 * 128; idx += 256) {
                int b = idx >> 7, k4 = idx & 127;
                sH4[b * 129 + k4] = Hg[b * 128 + k4];
            }
        }
        __syncthreads();

        // gate = xp + w_hh . h_prev
        const float* xpp = g_xp + ((dir * NS + ts) * NG + grow) * NB;
        float xr0 = xpp[bg], xr1 = xpp[bg + 8], xr2 = xpp[bg + 16], xr3 = xpp[bg + 24];

        const float4* wr = reinterpret_cast<const float4*>(sW) + r * 129;
        const float4* h0 = reinterpret_cast<const float4*>(sH) + bg * 129;
        const float4* h1 = h0 + 8 * 129;
        const float4* h2 = h0 + 16 * 129;
        const float4* h3 = h0 + 24 * 129;
        ULL a00 = 0, a01 = 0, a10 = 0, a11 = 0, a20 = 0, a21 = 0, a30 = 0, a31 = 0;
        #pragma unroll 4
        for (int k4 = 0; k4 < 128; ++k4) {
            F4U w; w.f = wr[k4];
            F4U h;
            h.f = h0[k4]; fma2(a00, w.u[0], h.u[0]); fma2(a01, w.u[1], h.u[1]);
            h.f = h1[k4]; fma2(a10, w.u[0], h.u[0]); fma2(a11, w.u[1], h.u[1]);
            h.f = h2[k4]; fma2(a20, w.u[0], h.u[0]); fma2(a21, w.u[1], h.u[1]);
            h.f = h3[k4]; fma2(a30, w.u[0], h.u[0]); fma2(a31, w.u[1], h.u[1]);
        }
        {
            F2U p, q;
            p.u = a00; q.u = a01; sG[r * 33 + bg]      = p.f.x + p.f.y + q.f.x + q.f.y + xr0;
            p.u = a10; q.u = a11; sG[r * 33 + bg + 8]  = p.f.x + p.f.y + q.f.x + q.f.y + xr1;
            p.u = a20; q.u = a21; sG[r * 33 + bg + 16] = p.f.x + p.f.y + q.f.x + q.f.y + xr2;
            p.u = a30; q.u = a31; sG[r * 33 + bg + 24] = p.f.x + p.f.y + q.f.x + q.f.y + xr3;
        }
        __syncthreads();

        // LSTM cell update for this CTA's 8 units x 32 batches
        {
            float gi = sG[ui * 33 + cb];
            float gf = sG[(8 + ui) * 33 + cb];
            float gg = sG[(16 + ui) * 33 + cb];
            float go = sG[(24 + ui) * 33 + cb];
            float c  = sC[ui * 32 + cb];
            float si = 1.f / (1.f + __expf(-gi));
            float sf = 1.f / (1.f + __expf(-gf));
            float so = 1.f / (1.f + __expf(-go));
            c = sf * c + si * tanhf(gg);
            sC[ui * 32 + cb] = c;
            float hv = so * tanhf(c);
            g_h[((dir * 2 + (step & 1)) * 32 + cb) * NH + u0 + ui] = hv;
            g_hs[((dir * NS + ts) * 32 + cb) * NH + u0 + ui] = hv;
        }
        __syncthreads();

        // 64-CTA barrier (per direction)
        if (tid == 0) {
            __threadfence();
            unsigned tgt = base_gen + (unsigned)step + 1u;
            unsigned prev = atomicAdd(&g_bar_cnt[dir], 1u);
            if (prev == 63u) {
                g_bar_cnt[dir] = 0u;
                __threadfence();
                atomicExch(&g_bar_gen[dir], tgt);
            } else {
                while (*(volatile unsigned*)&g_bar_gen[dir] < tgt) __nanosleep(64);
            }
            __threadfence();
        }
        __syncthreads();
    }
}

// ============================================================
// Kernel 4: emissions = [h_f | h_b] @ lin_w^T + lin_b
// grid 8192 (s*32+b), block 96
// ============================================================
__global__ void k_emis(const float* __restrict__ lin_w, const float* __restrict__ lin_b) {
    __shared__ float hv[1024];
    __shared__ float part[90];
    const int row = blockIdx.x;
    const int s = row >> 5, b = row & 31;
    const int tid = threadIdx.x;
    for (int idx = tid; idx < 1024; idx += 96) {
        int dr = idx >> 9, u = idx & 511;
        hv[idx] = g_hs[((dr * NS + s) * 32 + b) * NH + u];
    }
    __syncthreads();
    if (tid < 90) {
        int tag = tid >> 1, half = tid & 1;
        const float4* wv = reinterpret_cast<const float4*>(lin_w + tag * 1024 + half * 512);
        const float4* hp = reinterpret_cast<const float4*>(hv + half * 512);
        float acc = 0.f;
        #pragma unroll 4
        for (int q = 0; q < 128; ++q) {
            float4 a = wv[q], c = hp[q];
            acc += a.x * c.x + a.y * c.y + a.z * c.z + a.w * c.w;
        }
        part[tid] = acc;
    }
    __syncthreads();
    if (tid < NT)
        g_em[(b * NS + s) * NT + tid] = part[tid * 2] + part[tid * 2 + 1] + lin_b[tid];
}

// ============================================================
// Kernel 5: CRF forward algorithm + gold score.  grid 32, block 64
// ============================================================
__global__ void k_crf(const int* __restrict__ tags,
                      const float* __restrict__ start_t,
                      const float* __restrict__ end_t,
                      const float* __restrict__ trans)
{
    __shared__ float tr[NT * NT];
    __shared__ float al[2][48];
    __shared__ float red[64];
    __shared__ float s_score;
    const int b = blockIdx.x, tid = threadIdx.x;
    for (int i = tid; i < NT * NT; i += 64) tr[i] = trans[i];
    const float* em = g_em + b * NS * NT;
    const int* tg = tags + b * NS;

    float sc = 0.f;
    for (int s = tid; s < NS; s += 64) {
        int t = tg[s];
        sc += em[s * NT + t];
        if (s > 0) sc += trans[tg[s - 1] * NT + t];
    }
    red[tid] = sc;
    __syncthreads();
    if (tid == 0) {
        float tot = 0.f;
        for (int i = 0; i < 64; ++i) tot += red[i];
        tot += start_t[tg[0]] + end_t[tg[NS - 1]];
        s_score = tot;
    }
    if (tid < NT) al[0][tid] = start_t[tid] + em[tid];
    __syncthreads();

    int cur = 0;
    for (int s = 1; s < NS; ++s) {
        if (tid < NT) {
            const float* ao = al[cur];
            float m = -1e30f;
            #pragma unroll 5
            for (int j = 0; j < NT; ++j) m = fmaxf(m, ao[j] + tr[j * NT + tid]);
            float sum = 0.f;
            #pragma unroll 5
            for (int j = 0; j < NT; ++j) sum += __expf(ao[j] + tr[j * NT + tid] - m);
            al[cur ^ 1][tid] = m + __logf(sum) + em[s * NT + tid];
        }
        cur ^= 1;
        __syncthreads();
    }
    if (tid == 0) {
        float m = -1e30f;
        for (int t = 0; t < NT; ++t) m = fmaxf(m, al[cur][t] + end_t[t]);
        float sum = 0.f;
        for (int t = 0; t < NT; ++t) sum += __expf(al[cur][t] + end_t[t] - m);
        float logZ = m + __logf(sum);
        g_loss[b] = logZ - s_score;
    }
}

// ============================================================
// Kernel 6: deterministic fixed-order mean
// ============================================================
__global__ void k_final(float* out) {
    if (threadIdx.x == 0) {
        float t = 0.f;
        for (int b = 0; b < NB; ++b) t += g_loss[b];
        out[0] = t * (1.f / (float)NB);
    }
}

// ============================================================
extern "C" void kernel_launch(void* const* d_in, const int* in_sizes, int n_in,
                              void* d_out, int out_size) {
    const int*   x       = (const int*)d_in[0];
    const int*   tags    = (const int*)d_in[1];
    const float* emb     = (const float*)d_in[2];
    const float* w_ih_f  = (const float*)d_in[3];
    const float* w_hh_f  = (const float*)d_in[4];
    const float* b_f     = (const float*)d_in[5];
    const float* w_ih_b  = (const float*)d_in[6];
    const float* w_hh_b  = (const float*)d_in[7];
    const float* b_b     = (const float*)d_in[8];
    const float* lin_w   = (const float*)d_in[9];
    const float* lin_b   = (const float*)d_in[10];
    const float* start_t = (const float*)d_in[11];
    const float* end_t   = (const float*)d_in[12];
    const float* trans   = (const float*)d_in[13];
    float* out = (float*)d_out;
    (void)in_sizes; (void)n_in; (void)out_size;

    cudaFuncSetAttribute(k_lstm, cudaFuncAttributeMaxDynamicSharedMemorySize, 137344);

    k_gather<<<NS * NB, 64>>>(x, emb);
    k_inproj<<<dim3(32, NS, 2), 256>>>(w_ih_f, b_f, w_ih_b, b_b);
    k_lstm<<<128, 256, 137344>>>(w_hh_f, w_hh_b);
    k_emis<<<NS * NB, 96>>>(lin_w, lin_b);
    k_crf<<<NB, 64>>>(tags, start_t, end_t, trans);
    k_final<<<1, 32>>>(out);
}

// round 9
// speedup vs baseline: 1.6817x; 1.6817x over previous
#include <cuda_runtime.h>
#include <cuda_bf16.h>

typedef unsigned long long ULL;

#define NB 32        // batch
#define NS 256       // seq len
#define NE 256       // emb
#define NH 512       // hidden
#define NT 45        // tags
#define NG 2048      // 4*NH

// ---------------- scratch (static device globals: allowed) ----------------
__device__ float g_embeds[NS * NB * NE];           // [s][b][e]     8 MB
__device__ float g_xp[2 * NS * NG * NB];           // [dir][s][j][b] 128 MB
__device__ float g_h[2 * 2 * NB * NH];             // [dir][parity][b][k]
__device__ float g_hs[2 * NS * NB * NH];           // [dir][s][b][k] 32 MB
__device__ float g_em[NB * NS * NT];               // [b][s][t]
__device__ float g_loss[NB];
__device__ unsigned g_bar_cnt[2];
__device__ unsigned g_bar_gen[2];

// ---------------- f32x2 packed FMA ----------------
__device__ __forceinline__ void fma2(ULL &d, ULL a, ULL b) {
    asm("fma.rn.f32x2 %0, %1, %2, %0;" : "+l"(d) : "l"(a), "l"(b));
}
union F4U { float4 f; ULL u[2]; };
union F2U { ULL u; float2 f; };

// ============================================================
// Kernel 1: embedding gather.  grid 8192, block 64
// ============================================================
__global__ void k_gather(const int* __restrict__ x, const float* __restrict__ emb) {
    int row = blockIdx.x;                 // row = s*32 + b
    int s = row >> 5, b = row & 31;
    int tok = x[b * NS + s];
    const float4* src = reinterpret_cast<const float4*>(emb) + tok * (NE / 4);
    float4* dst = reinterpret_cast<float4*>(g_embeds) + row * (NE / 4);
    dst[threadIdx.x] = src[threadIdx.x];
}

// ============================================================
// Kernel 2: input projection GEMM (+bias).
// xp[dir][s][j][b] = sum_e w_ih[dir][j][e]*embeds[s][b][e] + bias[j]
// grid (16, 256, 2), block 256. CTA tile 128j x 32b, K-tiles of 64.
// Register tile per thread: 4 j-rows x 4 batches.
// ============================================================
__global__ __launch_bounds__(256) void k_inproj(
    const float* __restrict__ w_f, const float* __restrict__ bias_f,
    const float* __restrict__ w_b, const float* __restrict__ bias_b)
{
    __shared__ float sW[128 * 66];
    __shared__ float sX[32 * 66];
    const int jb  = blockIdx.x * 128;
    const int s   = blockIdx.y;
    const int dir = blockIdx.z;
    const float* W    = dir ? w_b : w_f;
    const float* bias = dir ? bias_b : bias_f;
    const int tid = threadIdx.x;
    const int tx = tid & 7;     // batches tx + 8m
    const int ty = tid >> 3;    // j rows ty + 32i

    ULL acc[4][4] = {};   // [i: j-row][m: batch]
    for (int kt = 0; kt < 4; ++kt) {
        const float2* Wg = reinterpret_cast<const float2*>(W);
        float2* sW2 = reinterpret_cast<float2*>(sW);
        #pragma unroll
        for (int i = 0; i < 16; ++i) {
            int idx = tid + 256 * i;
            int r = idx >> 5, c = idx & 31;
            sW2[r * 33 + c] = Wg[(jb + r) * 128 + kt * 32 + c];
        }
        const float2* Xg = reinterpret_cast<const float2*>(g_embeds);
        float2* sX2 = reinterpret_cast<float2*>(sX);
        #pragma unroll
        for (int i = 0; i < 4; ++i) {
            int idx = tid + 256 * i;
            int r = idx >> 5, c = idx & 31;
            sX2[r * 33 + c] = Xg[(s * 32 + r) * 128 + kt * 32 + c];
        }
        __syncthreads();
        const ULL* Wu = reinterpret_cast<const ULL*>(sW);
        const ULL* Xu = reinterpret_cast<const ULL*>(sX);
        #pragma unroll 8
        for (int kp = 0; kp < 32; ++kp) {
            ULL xm[4], wi[4];
            #pragma unroll
            for (int m = 0; m < 4; ++m) xm[m] = Xu[(tx + 8 * m) * 33 + kp];
            #pragma unroll
            for (int i = 0; i < 4; ++i) wi[i] = Wu[(ty + 32 * i) * 33 + kp];
            #pragma unroll
            for (int i = 0; i < 4; ++i)
                #pragma unroll
                for (int m = 0; m < 4; ++m)
                    fma2(acc[i][m], wi[i], xm[m]);
        }
        __syncthreads();
    }
    #pragma unroll
    for (int i = 0; i < 4; ++i) {
        int j = jb + ty + 32 * i;
        float bv = bias[j];
        float* outp = g_xp + ((dir * NS + s) * NG + j) * NB;
        #pragma unroll
        for (int m = 0; m < 4; ++m) {
            F2U a; a.u = acc[i][m];
            outp[tx + 8 * m] = a.f.x + a.f.y + bv;
        }
    }
}

// ============================================================
// Kernel 3: persistent bidirectional LSTM recurrence.
// grid 128 (64 CTAs/dir, each owns 8 hidden units = 32 gate rows),
// block 256, dyn smem 154240 B -> 1 CTA/SM, all co-resident.
// Dot phase: 4-way K-split, (4 rows x 4 batches)/thread register tile,
// partials reduced through smem. One 64-CTA barrier per step.
// ============================================================
__global__ __launch_bounds__(256, 1) void k_lstm(
    const float* __restrict__ whh_f, const float* __restrict__ whh_b)
{
    extern __shared__ float sm[];
    float* sW = sm;               // 32 rows x 516 floats (pitch 129 float4)
    float* sH = sm + 16512;       // 32 x 516
    float* sP = sm + 33024;       // 4 x 32 x 33 = 4224
    float* sG = sm + 37248;       // 32 x 33 = 1056
    float* sC = sm + 38304;       // 256
    const int tid = threadIdx.x;
    const int dir = blockIdx.x >> 6;
    const int d   = blockIdx.x & 63;
    const int u0  = d * 8;
    const float* W = dir ? whh_b : whh_f;

    // load this CTA's 32 gate rows of w_hh into smem (resident all 256 steps)
    {
        const float4* Wg = reinterpret_cast<const float4*>(W);
        float4* sW4 = reinterpret_cast<float4*>(sW);
        for (int idx = tid; idx < 32 * 128; idx += 256) {
            int r = idx >> 7, k4 = idx & 127;
            int grow = ((r >> 3) << 9) + u0 + (r & 7);
            sW4[r * 129 + k4] = Wg[grow * 128 + k4];
        }
    }
    for (int idx = tid; idx < 32 * 516; idx += 256) sH[idx] = 0.f;
    sC[tid] = 0.f;
    __shared__ unsigned s_base;
    if (tid == 0) s_base = *(volatile unsigned*)&g_bar_gen[dir];
    __syncthreads();
    const unsigned base_gen = s_base;

    // dot-phase mapping: K-group g, rows rt+8i, batches bt+8j
    const int g   = tid >> 6;
    const int wI  = tid & 63;
    const int rt  = wI >> 3;
    const int bt  = wI & 7;
    const int k4b = g * 32;
    // combine mapping: gate-row cr, batches cb0..cb0+3
    const int cr  = tid >> 3;
    const int cb0 = (tid & 7) * 4;
    const int growc = ((cr >> 3) << 9) + u0 + (cr & 7);
    // cell mapping
    const int cb = tid >> 3;
    const int ui = tid & 7;

    float4* sW4 = reinterpret_cast<float4*>(sW);
    float4* sH4 = reinterpret_cast<float4*>(sH);

    for (int step = 0; step < NS; ++step) {
        const int ts = dir ? (NS - 1 - step) : step;

        // prefetch xp for combine phase (consumed ~8k cycles later)
        float4 xv = *reinterpret_cast<const float4*>(
            g_xp + ((dir * NS + ts) * NG + growc) * NB + cb0);

        if (step > 0) {
            const int p = (step - 1) & 1;
            const float4* Hg = reinterpret_cast<const float4*>(g_h) + (dir * 2 + p) * 32 * 128;
            for (int idx = tid; idx < 32 * 128; idx += 256) {
                int b = idx >> 7, k4 = idx & 127;
                sH4[b * 129 + k4] = Hg[b * 128 + k4];
            }
        }
        __syncthreads();

        // dot: 16 partial dot-products over this thread's K quarter
        {
            const float4* w0 = sW4 + (rt     ) * 129 + k4b;
            const float4* w1 = sW4 + (rt +  8) * 129 + k4b;
            const float4* w2 = sW4 + (rt + 16) * 129 + k4b;
            const float4* w3 = sW4 + (rt + 24) * 129 + k4b;
            const float4* h0 = sH4 + (bt     ) * 129 + k4b;
            const float4* h1 = sH4 + (bt +  8) * 129 + k4b;
            const float4* h2 = sH4 + (bt + 16) * 129 + k4b;
            const float4* h3 = sH4 + (bt + 24) * 129 + k4b;
            ULL acc[4][4] = {};
            #pragma unroll 4
            for (int k4 = 0; k4 < 32; ++k4) {
                F4U w[4], h[4];
                w[0].f = w0[k4]; w[1].f = w1[k4]; w[2].f = w2[k4]; w[3].f = w3[k4];
                h[0].f = h0[k4]; h[1].f = h1[k4]; h[2].f = h2[k4]; h[3].f = h3[k4];
                #pragma unroll
                for (int i = 0; i < 4; ++i)
                    #pragma unroll
                    for (int j = 0; j < 4; ++j) {
                        fma2(acc[i][j], w[i].u[0], h[j].u[0]);
                        fma2(acc[i][j], w[i].u[1], h[j].u[1]);
                    }
            }
            #pragma unroll
            for (int i = 0; i < 4; ++i)
                #pragma unroll
                for (int j = 0; j < 4; ++j) {
                    F2U t; t.u = acc[i][j];
                    sP[(g * 32 + rt + 8 * i) * 33 + bt + 8 * j] = t.f.x + t.f.y;
                }
        }
        __syncthreads();

        // combine: gate = sum of 4 K-partials + xp
        {
            float4 gs = xv;
            #pragma unroll
            for (int gg = 0; gg < 4; ++gg) {
                const float* pp = sP + (gg * 32 + cr) * 33 + cb0;
                gs.x += pp[0]; gs.y += pp[1]; gs.z += pp[2]; gs.w += pp[3];
            }
            float* gp = sG + cr * 33 + cb0;
            gp[0] = gs.x; gp[1] = gs.y; gp[2] = gs.z; gp[3] = gs.w;
        }
        __syncthreads();

        // LSTM cell update: 8 units x 32 batches
        {
            float gi = sG[ui * 33 + cb];
            float gf = sG[(8 + ui) * 33 + cb];
            float gg = sG[(16 + ui) * 33 + cb];
            float go = sG[(24 + ui) * 33 + cb];
            float c  = sC[ui * 32 + cb];
            float si = 1.f / (1.f + __expf(-gi));
            float sf = 1.f / (1.f + __expf(-gf));
            float so = 1.f / (1.f + __expf(-go));
            c = sf * c + si * tanhf(gg);
            sC[ui * 32 + cb] = c;
            float hv = so * tanhf(c);
            g_h[((dir * 2 + (step & 1)) * 32 + cb) * NH + u0 + ui] = hv;
            g_hs[((dir * NS + ts) * 32 + cb) * NH + u0 + ui] = hv;
        }
        __syncthreads();

        // 64-CTA barrier (per direction)
        if (tid == 0) {
            __threadfence();
            unsigned tgt = base_gen + (unsigned)step + 1u;
            unsigned prev = atomicAdd(&g_bar_cnt[dir], 1u);
            if (prev == 63u) {
                g_bar_cnt[dir] = 0u;
                __threadfence();
                atomicExch(&g_bar_gen[dir], tgt);
            } else {
                while (*(volatile unsigned*)&g_bar_gen[dir] < tgt) __nanosleep(64);
            }
            __threadfence();
        }
        __syncthreads();
    }
}

// ============================================================
// Kernel 4: emissions GEMM: em[row][t] = H[row][1024] . lin_w[t][1024] + b
// grid 128 (64 rows each), block 256, smem-tiled, (4x4) register tile.
// ============================================================
__global__ __launch_bounds__(256, 1) void k_emis(
    const float* __restrict__ lin_w, const float* __restrict__ lin_b)
{
    extern __shared__ float es[];
    float* sH = es;                 // 64 rows x 260 floats (pitch 65 float4)
    float* sW = es + 16640;         // 48 rows x 260
    float4* sH4 = reinterpret_cast<float4*>(sH);
    float4* sW4 = reinterpret_cast<float4*>(sW);
    const int tid = threadIdx.x;
    const int R0 = blockIdx.x * 64;
    const int rt = tid & 15;        // rows rt + 16i
    const int tt = tid >> 4;        // tags tt + 12j (active tt<12)

    ULL acc[4][4] = {};             // [i: row][j: tag]
    for (int kt = 0; kt < 4; ++kt) {
        const int dirq = kt >> 1;
        const int koff = (kt & 1) * 64;
        const float4* Hg = reinterpret_cast<const float4*>(g_hs);
        #pragma unroll
        for (int i = 0; i < 16; ++i) {
            int idx = tid + 256 * i;
            int r = idx >> 6, c = idx & 63;
            int row = R0 + r, s = row >> 5, b = row & 31;
            sH4[r * 65 + c] = Hg[((dirq * NS + s) * 32 + b) * 128 + koff + c];
        }
        const float4* Wg = reinterpret_cast<const float4*>(lin_w);
        #pragma unroll
        for (int i = 0; i < 12; ++i) {
            int idx = tid + 256 * i;
            int r = idx >> 6, c = idx & 63;
            float4 v = make_float4(0.f, 0.f, 0.f, 0.f);
            if (r < NT) v = Wg[r * 256 + kt * 64 + c];
            sW4[r * 65 + c] = v;
        }
        __syncthreads();
        if (tt < 12) {
            const float4* hp0 = sH4 + (rt     ) * 65;
            const float4* hp1 = sH4 + (rt + 16) * 65;
            const float4* hp2 = sH4 + (rt + 32) * 65;
            const float4* hp3 = sH4 + (rt + 48) * 65;
            const float4* wp0 = sW4 + (tt     ) * 65;
            const float4* wp1 = sW4 + (tt + 12) * 65;
            const float4* wp2 = sW4 + (tt + 24) * 65;
            const float4* wp3 = sW4 + (tt + 36) * 65;
            #pragma unroll 4
            for (int k4 = 0; k4 < 64; ++k4) {
                F4U h[4], w[4];
                h[0].f = hp0[k4]; h[1].f = hp1[k4]; h[2].f = hp2[k4]; h[3].f = hp3[k4];
                w[0].f = wp0[k4]; w[1].f = wp1[k4]; w[2].f = wp2[k4]; w[3].f = wp3[k4];
                #pragma unroll
                for (int i = 0; i < 4; ++i)
                    #pragma unroll
                    for (int j = 0; j < 4; ++j) {
                        fma2(acc[i][j], h[i].u[0], w[j].u[0]);
                        fma2(acc[i][j], h[i].u[1], w[j].u[1]);
                    }
            }
        }
        __syncthreads();
    }
    if (tt < 12) {
        #pragma unroll
        for (int i = 0; i < 4; ++i) {
            int row = R0 + rt + 16 * i;
            int s = row >> 5, b = row & 31;
            #pragma unroll
            for (int j = 0; j < 4; ++j) {
                int t = tt + 12 * j;
                if (t < NT) {
                    F2U u; u.u = acc[i][j];
                    g_em[(b * NS + s) * NT + t] = u.f.x + u.f.y + lin_b[t];
                }
            }
        }
    }
}

// ============================================================
// Kernel 5: CRF forward algorithm + gold score.  grid 32, block 64
// ============================================================
__global__ void k_crf(const int* __restrict__ tags,
                      const float* __restrict__ start_t,
                      const float* __restrict__ end_t,
                      const float* __restrict__ trans)
{
    __shared__ float tr[NT * NT];
    __shared__ float al[2][48];
    __shared__ float red[64];
    __shared__ float s_score;
    const int b = blockIdx.x, tid = threadIdx.x;
    for (int i = tid; i < NT * NT; i += 64) tr[i] = trans[i];
    const float* em = g_em + b * NS * NT;
    const int* tg = tags + b * NS;

    float sc = 0.f;
    for (int s = tid; s < NS; s += 64) {
        int t = tg[s];
        sc += em[s * NT + t];
        if (s > 0) sc += trans[tg[s - 1] * NT + t];
    }
    red[tid] = sc;
    __syncthreads();
    if (tid == 0) {
        float tot = 0.f;
        for (int i = 0; i < 64; ++i) tot += red[i];
        tot += start_t[tg[0]] + end_t[tg[NS - 1]];
        s_score = tot;
    }
    if (tid < NT) al[0][tid] = start_t[tid] + em[tid];
    __syncthreads();

    int cur = 0;
    for (int s = 1; s < NS; ++s) {
        if (tid < NT) {
            const float* ao = al[cur];
            float m = -1e30f;
            #pragma unroll 5
            for (int j = 0; j < NT; ++j) m = fmaxf(m, ao[j] + tr[j * NT + tid]);
            float sum = 0.f;
            #pragma unroll 5
            for (int j = 0; j < NT; ++j) sum += __expf(ao[j] + tr[j * NT + tid] - m);
            al[cur ^ 1][tid] = m + __logf(sum) + em[s * NT + tid];
        }
        cur ^= 1;
        __syncthreads();
    }
    if (tid == 0) {
        float m = -1e30f;
        for (int t = 0; t < NT; ++t) m = fmaxf(m, al[cur][t] + end_t[t]);
        float sum = 0.f;
        for (int t = 0; t < NT; ++t) sum += __expf(al[cur][t] + end_t[t] - m);
        float logZ = m + __logf(sum);
        g_loss[b] = logZ - s_score;
    }
}

// ============================================================
// Kernel 6: deterministic fixed-order mean
// ============================================================
__global__ void k_final(float* out) {
    if (threadIdx.x == 0) {
        float t = 0.f;
        for (int b = 0; b < NB; ++b) t += g_loss[b];
        out[0] = t * (1.f / (float)NB);
    }
}

// ============================================================
extern "C" void kernel_launch(void* const* d_in, const int* in_sizes, int n_in,
                              void* d_out, int out_size) {
    const int*   x       = (const int*)d_in[0];
    const int*   tags    = (const int*)d_in[1];
    const float* emb     = (const float*)d_in[2];
    const float* w_ih_f  = (const float*)d_in[3];
    const float* w_hh_f  = (const float*)d_in[4];
    const float* b_f     = (const float*)d_in[5];
    const float* w_ih_b  = (const float*)d_in[6];
    const float* w_hh_b  = (const float*)d_in[7];
    const float* b_b     = (const float*)d_in[8];
    const float* lin_w   = (const float*)d_in[9];
    const float* lin_b   = (const float*)d_in[10];
    const float* start_t = (const float*)d_in[11];
    const float* end_t   = (const float*)d_in[12];
    const float* trans   = (const float*)d_in[13];
    float* out = (float*)d_out;
    (void)in_sizes; (void)n_in; (void)out_size;

    cudaFuncSetAttribute(k_lstm, cudaFuncAttributeMaxDynamicSharedMemorySize, 154240);
    cudaFuncSetAttribute(k_emis, cudaFuncAttributeMaxDynamicSharedMemorySize, 116480);

    k_gather<<<NS * NB, 64>>>(x, emb);
    k_inproj<<<dim3(16, NS, 2), 256>>>(w_ih_f, b_f, w_ih_b, b_b);
    k_lstm<<<128, 256, 154240>>>(w_hh_f, w_hh_b);
    k_emis<<<128, 256, 116480>>>(lin_w, lin_b);
    k_crf<<<NB, 64>>>(tags, start_t, end_t, trans);
    k_final<<<1, 32>>>(out);
}

// round 12
// speedup vs baseline: 1.8070x; 1.0745x over previous
#include <cuda_runtime.h>
#include <cuda_bf16.h>

typedef unsigned long long ULL;

#define NB 32        // batch
#define NS 256       // seq len
#define NE 256       // emb
#define NH 512       // hidden
#define NT 45        // tags
#define NG 2048      // 4*NH

// ---------------- scratch (static device globals: allowed) ----------------
__device__ float g_embeds[NS * NB * NE];           // [s][b][e]     8 MB
__device__ float g_xp[2 * NS * NG * NB];           // [dir][s][j][b] 128 MB
__device__ float g_hs[2 * NS * NB * NH];           // [dir][s][b][k] 32 MB
__device__ float g_em[NB * NS * NT];               // [b][s][t]
__device__ float g_loss[NB];
__device__ unsigned g_flag[2][64 * 32];            // per-CTA step flags, 128B padded

// ---------------- f32x2 packed FMA ----------------
__device__ __forceinline__ void fma2(ULL &d, ULL a, ULL b) {
    asm("fma.rn.f32x2 %0, %1, %2, %0;" : "+l"(d) : "l"(a), "l"(b));
}
union F4U { float4 f; ULL u[2]; };
union F2U { ULL u; float2 f; };

// ============================================================
// Kernel 1: embedding gather.  grid 8192, block 64
// ============================================================
__global__ void k_gather(const int* __restrict__ x, const float* __restrict__ emb) {
    int row = blockIdx.x;                 // row = s*32 + b
    int s = row >> 5, b = row & 31;
    int tok = x[b * NS + s];
    const float4* src = reinterpret_cast<const float4*>(emb) + tok * (NE / 4);
    float4* dst = reinterpret_cast<float4*>(g_embeds) + row * (NE / 4);
    dst[threadIdx.x] = src[threadIdx.x];
}

// ============================================================
// Kernel 2: input projection GEMM (+bias), float4 smem tiles.
// xp[dir][s][j][b] = sum_e w_ih[dir][j][e]*embeds[s][b][e] + bias[j]
// grid (16, 256, 2), block 256. CTA tile 128j x 32b, K-tiles of 64 floats.
// Register tile per thread: 4 j-rows x 4 batches.
// ============================================================
__global__ __launch_bounds__(256) void k_inproj(
    const float* __restrict__ w_f, const float* __restrict__ bias_f,
    const float* __restrict__ w_b, const float* __restrict__ bias_b)
{
    __shared__ float4 sW4[128 * 17];
    __shared__ float4 sX4[32 * 17];
    const int jb  = blockIdx.x * 128;
    const int s   = blockIdx.y;
    const int dir = blockIdx.z;
    const float* W    = dir ? w_b : w_f;
    const float* bias = dir ? bias_b : bias_f;
    const int tid = threadIdx.x;
    const int tx = tid & 7;     // batches tx + 8m
    const int ty = tid >> 3;    // j rows ty + 32i

    const float4* Wg = reinterpret_cast<const float4*>(W);
    const float4* Xg = reinterpret_cast<const float4*>(g_embeds);

    ULL acc[4][4] = {};   // [i: j-row][m: batch]
    for (int kt = 0; kt < 4; ++kt) {
        #pragma unroll
        for (int i = 0; i < 8; ++i) {
            int idx = tid + 256 * i;
            int r = idx >> 4, c = idx & 15;
            sW4[r * 17 + c] = Wg[(jb + r) * 64 + kt * 16 + c];
        }
        #pragma unroll
        for (int i = 0; i < 2; ++i) {
            int idx = tid + 256 * i;
            int r = idx >> 4, c = idx & 15;
            sX4[r * 17 + c] = Xg[(s * 32 + r) * 64 + kt * 16 + c];
        }
        __syncthreads();
        #pragma unroll 4
        for (int k4 = 0; k4 < 16; ++k4) {
            F4U xm[4], wi[4];
            #pragma unroll
            for (int m = 0; m < 4; ++m) xm[m].f = sX4[(tx + 8 * m) * 17 + k4];
            #pragma unroll
            for (int i = 0; i < 4; ++i) wi[i].f = sW4[(ty + 32 * i) * 17 + k4];
            #pragma unroll
            for (int i = 0; i < 4; ++i)
                #pragma unroll
                for (int m = 0; m < 4; ++m) {
                    fma2(acc[i][m], wi[i].u[0], xm[m].u[0]);
                    fma2(acc[i][m], wi[i].u[1], xm[m].u[1]);
                }
        }
        __syncthreads();
    }
    #pragma unroll
    for (int i = 0; i < 4; ++i) {
        int j = jb + ty + 32 * i;
        float bv = bias[j];
        float* outp = g_xp + ((dir * NS + s) * NG + j) * NB;
        #pragma unroll
        for (int m = 0; m < 4; ++m) {
            F2U a; a.u = acc[i][m];
            outp[tx + 8 * m] = a.f.x + a.f.y + bv;
        }
    }
}

// ============================================================
// Kernel 3: persistent bidirectional LSTM recurrence.
// grid 128 (64 CTAs/dir, each owns 8 hidden units = 32 gate rows),
// block 256, dyn smem 148992 B -> 1 CTA/SM, all co-resident.
// Flag-array barrier (parallel arrivals + parallel polling).
// h exchanged via g_hs directly (no extra buffer). Cell state in regs.
// ============================================================
__global__ __launch_bounds__(256, 1) void k_lstm(
    const float* __restrict__ whh_f, const float* __restrict__ whh_b)
{
    extern __shared__ float sm[];
    float* sW = sm;               // 32 rows x 516 floats (pitch 129 float4)
    float* sH = sm + 16512;       // 32 x 516
    float* sP = sm + 33024;       // 4 x 32 x 33 = 4224
    const int tid = threadIdx.x;
    const int dir = blockIdx.x >> 6;
    const int d   = blockIdx.x & 63;
    const int u0  = d * 8;
    const float* W = dir ? whh_b : whh_f;

    // load this CTA's 32 gate rows of w_hh into smem (resident all 256 steps)
    {
        const float4* Wg = reinterpret_cast<const float4*>(W);
        float4* sW4 = reinterpret_cast<float4*>(sW);
        for (int idx = tid; idx < 32 * 128; idx += 256) {
            int r = idx >> 7, k4 = idx & 127;
            int grow = ((r >> 3) << 9) + u0 + (r & 7);
            sW4[r * 129 + k4] = Wg[grow * 128 + k4];
        }
    }
    for (int idx = tid; idx < 32 * 516; idx += 256) sH[idx] = 0.f;
    __shared__ unsigned s_base;
    if (tid == 0) s_base = *(volatile unsigned*)&g_flag[dir][d * 32];
    __syncthreads();
    const unsigned base_gen = s_base;

    // dot-phase mapping: K-group g, rows rt+8i, batches bt+8j
    const int g   = tid >> 6;
    const int wI  = tid & 63;
    const int rt  = wI >> 3;
    const int bt  = wI & 7;
    const int k4b = g * 32;
    // fused combine+cell mapping: batch cb (coalesced), unit ui
    const int cb = tid & 31;
    const int ui = tid >> 5;

    float4* sW4 = reinterpret_cast<float4*>(sW);
    float4* sH4 = reinterpret_cast<float4*>(sH);

    float c_reg = 0.f;            // persistent cell state for (ui, cb)

    for (int step = 0; step < NS; ++step) {
        const int ts = dir ? (NS - 1 - step) : step;

        // prefetch xp for the 4 gates of (ui, cb); consumed after dot phase
        const float* xpb = g_xp + (dir * NS + ts) * NG * NB;
        float xgi = xpb[(u0 + ui) * NB + cb];
        float xgf = xpb[(512 + u0 + ui) * NB + cb];
        float xgg = xpb[(1024 + u0 + ui) * NB + cb];
        float xgo = xpb[(1536 + u0 + ui) * NB + cb];

        if (step > 0) {
            const int tp = dir ? (ts + 1) : (ts - 1);
            const float4* Hg = reinterpret_cast<const float4*>(g_hs)
                             + (ULL)(dir * NS + tp) * 32 * 128;
            for (int idx = tid; idx < 32 * 128; idx += 256) {
                int b = idx >> 7, k4 = idx & 127;
                sH4[b * 129 + k4] = Hg[b * 128 + k4];
            }
        }
        __syncthreads();

        // dot: 16 partial dot-products over this thread's K quarter
        {
            const float4* w0 = sW4 + (rt     ) * 129 + k4b;
            const float4* w1 = sW4 + (rt +  8) * 129 + k4b;
            const float4* w2 = sW4 + (rt + 16) * 129 + k4b;
            const float4* w3 = sW4 + (rt + 24) * 129 + k4b;
            const float4* h0 = sH4 + (bt     ) * 129 + k4b;
            const float4* h1 = sH4 + (bt +  8) * 129 + k4b;
            const float4* h2 = sH4 + (bt + 16) * 129 + k4b;
            const float4* h3 = sH4 + (bt + 24) * 129 + k4b;
            ULL acc[4][4] = {};
            #pragma unroll 4
            for (int k4 = 0; k4 < 32; ++k4) {
                F4U w[4], h[4];
                w[0].f = w0[k4]; w[1].f = w1[k4]; w[2].f = w2[k4]; w[3].f = w3[k4];
                h[0].f = h0[k4]; h[1].f = h1[k4]; h[2].f = h2[k4]; h[3].f = h3[k4];
                #pragma unroll
                for (int i = 0; i < 4; ++i)
                    #pragma unroll
                    for (int j = 0; j < 4; ++j) {
                        fma2(acc[i][j], w[i].u[0], h[j].u[0]);
                        fma2(acc[i][j], w[i].u[1], h[j].u[1]);
                    }
            }
            #pragma unroll
            for (int i = 0; i < 4; ++i)
                #pragma unroll
                for (int j = 0; j < 4; ++j) {
                    F2U t; t.u = acc[i][j];
                    sP[(g * 32 + rt + 8 * i) * 33 + bt + 8 * j] = t.f.x + t.f.y;
                }
        }
        __syncthreads();

        // fused combine + LSTM cell for (ui, cb)
        {
            float gi = xgi, gf = xgf, gg = xgg, go = xgo;
            #pragma unroll
            for (int q = 0; q < 4; ++q) {
                gi += sP[(q * 32 +      ui) * 33 + cb];
                gf += sP[(q * 32 +  8 + ui) * 33 + cb];
                gg += sP[(q * 32 + 16 + ui) * 33 + cb];
                go += sP[(q * 32 + 24 + ui) * 33 + cb];
            }
            float si = 1.f / (1.f + __expf(-gi));
            float sf = 1.f / (1.f + __expf(-gf));
            float so = 1.f / (1.f + __expf(-go));
            c_reg = sf * c_reg + si * tanhf(gg);
            float hv = so * tanhf(c_reg);
            g_hs[((ULL)(dir * NS + ts) * 32 + cb) * NH + u0 + ui] = hv;
        }
        __syncthreads();

        // flag-array barrier: parallel arrival, parallel polling
        const unsigned tgt = base_gen + (unsigned)step + 1u;
        if (tid == 0) {
            __threadfence();                       // cumulative release
            *(volatile unsigned*)&g_flag[dir][d * 32] = tgt;
        }
        if (tid < 64) {
            while (*(volatile unsigned*)&g_flag[dir][tid * 32] < tgt) {}
            __threadfence();                       // acquire
        }
        __syncthreads();
    }
}

// ============================================================
// Kernel 4: emissions GEMM: em[row][t] = H[row][1024] . lin_w[t][1024] + b
// grid 128 (64 rows each), block 256, smem-tiled, (4x4) register tile.
// ============================================================
__global__ __launch_bounds__(256, 1) void k_emis(
    const float* __restrict__ lin_w, const float* __restrict__ lin_b)
{
    extern __shared__ float es[];
    float* sH = es;                 // 64 rows x 260 floats (pitch 65 float4)
    float* sW = es + 16640;         // 48 rows x 260
    float4* sH4 = reinterpret_cast<float4*>(sH);
    float4* sW4 = reinterpret_cast<float4*>(sW);
    const int tid = threadIdx.x;
    const int R0 = blockIdx.x * 64;
    const int rt = tid & 15;        // rows rt + 16i
    const int tt = tid >> 4;        // tags tt + 12j (active tt<12)

    ULL acc[4][4] = {};             // [i: row][j: tag]
    for (int kt = 0; kt < 4; ++kt) {
        const int dirq = kt >> 1;
        const int koff = (kt & 1) * 64;
        const float4* Hg = reinterpret_cast<const float4*>(g_hs);
        #pragma unroll
        for (int i = 0; i < 16; ++i) {
            int idx = tid + 256 * i;
            int r = idx >> 6, c = idx & 63;
            int row = R0 + r, s = row >> 5, b = row & 31;
            sH4[r * 65 + c] = Hg[((dirq * NS + s) * 32 + b) * 128 + koff + c];
        }
        const float4* Wg = reinterpret_cast<const float4*>(lin_w);
        #pragma unroll
        for (int i = 0; i < 12; ++i) {
            int idx = tid + 256 * i;
            int r = idx >> 6, c = idx & 63;
            float4 v = make_float4(0.f, 0.f, 0.f, 0.f);
            if (r < NT) v = Wg[r * 256 + kt * 64 + c];
            sW4[r * 65 + c] = v;
        }
        __syncthreads();
        if (tt < 12) {
            const float4* hp0 = sH4 + (rt     ) * 65;
            const float4* hp1 = sH4 + (rt + 16) * 65;
            const float4* hp2 = sH4 + (rt + 32) * 65;
            const float4* hp3 = sH4 + (rt + 48) * 65;
            const float4* wp0 = sW4 + (tt     ) * 65;
            const float4* wp1 = sW4 + (tt + 12) * 65;
            const float4* wp2 = sW4 + (tt + 24) * 65;
            const float4* wp3 = sW4 + (tt + 36) * 65;
            #pragma unroll 4
            for (int k4 = 0; k4 < 64; ++k4) {
                F4U h[4], w[4];
                h[0].f = hp0[k4]; h[1].f = hp1[k4]; h[2].f = hp2[k4]; h[3].f = hp3[k4];
                w[0].f = wp0[k4]; w[1].f = wp1[k4]; w[2].f = wp2[k4]; w[3].f = wp3[k4];
                #pragma unroll
                for (int i = 0; i < 4; ++i)
                    #pragma unroll
                    for (int j = 0; j < 4; ++j) {
                        fma2(acc[i][j], h[i].u[0], w[j].u[0]);
                        fma2(acc[i][j], h[i].u[1], w[j].u[1]);
                    }
            }
        }
        __syncthreads();
    }
    if (tt < 12) {
        #pragma unroll
        for (int i = 0; i < 4; ++i) {
            int row = R0 + rt + 16 * i;
            int s = row >> 5, b = row & 31;
            #pragma unroll
            for (int j = 0; j < 4; ++j) {
                int t = tt + 12 * j;
                if (t < NT) {
                    F2U u; u.u = acc[i][j];
                    g_em[(b * NS + s) * NT + t] = u.f.x + u.f.y + lin_b[t];
                }
            }
        }
    }
}

// ============================================================
// Kernel 5: CRF forward algorithm + gold score.  grid 32, block 64
// ============================================================
__global__ void k_crf(const int* __restrict__ tags,
                      const float* __restrict__ start_t,
                      const float* __restrict__ end_t,
                      const float* __restrict__ trans)
{
    __shared__ float tr[NT * NT];
    __shared__ float al[2][48];
    __shared__ float red[64];
    __shared__ float s_score;
    const int b = blockIdx.x, tid = threadIdx.x;
    for (int i = tid; i < NT * NT; i += 64) tr[i] = trans[i];
    const float* em = g_em + b * NS * NT;
    const int* tg = tags + b * NS;

    float sc = 0.f;
    for (int s = tid; s < NS; s += 64) {
        int t = tg[s];
        sc += em[s * NT + t];
        if (s > 0) sc += trans[tg[s - 1] * NT + t];
    }
    red[tid] = sc;
    __syncthreads();
    if (tid == 0) {
        float tot = 0.f;
        for (int i = 0; i < 64; ++i) tot += red[i];
        tot += start_t[tg[0]] + end_t[tg[NS - 1]];
        s_score = tot;
    }
    if (tid < NT) al[0][tid] = start_t[tid] + em[tid];
    __syncthreads();

    int cur = 0;
    for (int s = 1; s < NS; ++s) {
        if (tid < NT) {
            const float* ao = al[cur];
            // 4-way split accumulators to shorten serial dependence chains
            float m0 = -1e30f, m1 = -1e30f, m2 = -1e30f, m3 = -1e30f;
            #pragma unroll
            for (int j = 0; j < 44; j += 4) {
                m0 = fmaxf(m0, ao[j    ] + tr[(j    ) * NT + tid]);
                m1 = fmaxf(m1, ao[j + 1] + tr[(j + 1) * NT + tid]);
                m2 = fmaxf(m2, ao[j + 2] + tr[(j + 2) * NT + tid]);
                m3 = fmaxf(m3, ao[j + 3] + tr[(j + 3) * NT + tid]);
            }
            m0 = fmaxf(m0, ao[44] + tr[44 * NT + tid]);
            float m = fmaxf(fmaxf(m0, m1), fmaxf(m2, m3));
            float s0 = 0.f, s1 = 0.f, s2 = 0.f, s3 = 0.f;
            #pragma unroll
            for (int j = 0; j < 44; j += 4) {
                s0 += __expf(ao[j    ] + tr[(j    ) * NT + tid] - m);
                s1 += __expf(ao[j + 1] + tr[(j + 1) * NT + tid] - m);
                s2 += __expf(ao[j + 2] + tr[(j + 2) * NT + tid] - m);
                s3 += __expf(ao[j + 3] + tr[(j + 3) * NT + tid] - m);
            }
            s0 += __expf(ao[44] + tr[44 * NT + tid] - m);
            float sum = (s0 + s1) + (s2 + s3);
            al[cur ^ 1][tid] = m + __logf(sum) + em[s * NT + tid];
        }
        cur ^= 1;
        __syncthreads();
    }
    if (tid == 0) {
        float m = -1e30f;
        for (int t = 0; t < NT; ++t) m = fmaxf(m, al[cur][t] + end_t[t]);
        float sum = 0.f;
        for (int t = 0; t < NT; ++t) sum += __expf(al[cur][t] + end_t[t] - m);
        float logZ = m + __logf(sum);
        g_loss[b] = logZ - s_score;
    }
}

// ============================================================
// Kernel 6: deterministic fixed-order mean
// ============================================================
__global__ void k_final(float* out) {
    if (threadIdx.x == 0) {
        float t = 0.f;
        for (int b = 0; b < NB; ++b) t += g_loss[b];
        out[0] = t * (1.f / (float)NB);
    }
}

// ============================================================
extern "C" void kernel_launch(void* const* d_in, const int* in_sizes, int n_in,
                              void* d_out, int out_size) {
    const int*   x       = (const int*)d_in[0];
    const int*   tags    = (const int*)d_in[1];
    const float* emb     = (const float*)d_in[2];
    const float* w_ih_f  = (const float*)d_in[3];
    const float* w_hh_f  = (const float*)d_in[4];
    const float* b_f     = (const float*)d_in[5];
    const float* w_ih_b  = (const float*)d_in[6];
    const float* w_hh_b  = (const float*)d_in[7];
    const float* b_b     = (const float*)d_in[8];
    const float* lin_w   = (const float*)d_in[9];
    const float* lin_b   = (const float*)d_in[10];
    const float* start_t = (const float*)d_in[11];
    const float* end_t   = (const float*)d_in[12];
    const float* trans   = (const float*)d_in[13];
    float* out = (float*)d_out;
    (void)in_sizes; (void)n_in; (void)out_size;

    cudaFuncSetAttribute(k_lstm, cudaFuncAttributeMaxDynamicSharedMemorySize, 148992);
    cudaFuncSetAttribute(k_emis, cudaFuncAttributeMaxDynamicSharedMemorySize, 116480);

    k_gather<<<NS * NB, 64>>>(x, emb);
    k_inproj<<<dim3(16, NS, 2), 256>>>(w_ih_f, b_f, w_ih_b, b_b);
    k_lstm<<<128, 256, 148992>>>(w_hh_f, w_hh_b);
    k_emis<<<128, 256, 116480>>>(lin_w, lin_b);
    k_crf<<<NB, 64>>>(tags, start_t, end_t, trans);
    k_final<<<1, 32>>>(out);
}